// round 9
// baseline (speedup 1.0000x reference)
#include <cuda_runtime.h>
#include <cstdint>

#define IMW   1024
#define IMH   1024
#define HW    (1024*1024)
#define BATCH 16
#define NPIX  (16u*1024u*1024u)
#define TR    16           // output rows per edge block
#define WPR   32           // 32-bit words per row (1024/32)
#define MAIN_BLOCKS 888    // 148 SMs * 6 blocks (regs=40 -> 6 resident), ONE wave

// ---------------- device scratch (static; no allocations) ----------------
// All zero-initialized at module load; main_kernel's last block resets them
// after each replay, keeping the graph deterministic.
__device__ double        g_acc[4];                     // A0, B0, A1, B1
__device__ unsigned int  g_E;                          // edge pixel count
__device__ unsigned int  g_ticket;                     // last-block ticket
__device__ unsigned int  g_ebits[BATCH * IMH * WPR];   // packed edge mask (2 MB)
__device__ unsigned int  g_tbits[BATCH * IMH * WPR];   // packed target   (2 MB)

// ---------------- kernel 1: bitwise 11x11 edge detector -------------------
// edge(t)=0  iff  (t==1 AND all 11x11 window ==1, zero-padded)
//             or  (t==0 AND all 11x11 window ==0, zero-padded)
// => edge = (t & ~AND11x11) | (~t & OR11x11)   on packed bits.
__global__ __launch_bounds__(256) void edge_kernel(const int* __restrict__ target) {
    __shared__ unsigned sp[TR + 10][WPR];   // packed target rows (with halo)
    __shared__ unsigned sa[TR + 10][WPR];   // horizontal AND-11
    __shared__ unsigned so[TR + 10][WPR];   // horizontal OR-11

    const int b    = blockIdx.y;
    const int r0   = blockIdx.x * TR;
    const int tid  = threadIdx.x;
    const int lane = tid & 31;
    const int warp = tid >> 5;
    const int* tb  = target + (size_t)b * HW;

    // pack target -> bits: each thread builds one word from 8 independent
    // int4 loads (128B contiguous). No cross-lane dependency -> high MLP.
    for (int j = tid; j < (TR + 10) * WPR; j += 256) {
        const int lr = j >> 5, wc = j & 31;
        const int gr = r0 - 5 + lr;
        unsigned w = 0u;
        if (gr >= 0 && gr < IMH) {
            const int4* p4 = (const int4*)(tb + gr * IMW + wc * 32);
            #pragma unroll
            for (int k = 0; k < 8; k++) {
                const int4 v = __ldcs(p4 + k);
                w |= (v.x != 0 ? 1u : 0u) << (4 * k);
                w |= (v.y != 0 ? 2u : 0u) << (4 * k);
                w |= (v.z != 0 ? 4u : 0u) << (4 * k);
                w |= (v.w != 0 ? 8u : 0u) << (4 * k);
            }
        }
        sp[lr][wc] = w;
    }
    __syncthreads();

    // horizontal 11-tap AND/OR with funnel shifts across word boundaries
    for (int j = tid; j < (TR + 10) * WPR; j += 256) {
        const int lr = j >> 5, wc = j & 31;
        const unsigned c = sp[lr][wc];
        const unsigned l = (wc > 0)        ? sp[lr][wc - 1] : 0u;
        const unsigned r = (wc < WPR - 1)  ? sp[lr][wc + 1] : 0u;
        unsigned a = c, o = c;
        #pragma unroll
        for (int k = 1; k <= 5; k++) {
            const unsigned sr = __funnelshift_r(c, r, k);  // bit i <- col i+k
            const unsigned sl = __funnelshift_l(l, c, k);  // bit i <- col i-k
            a &= (sr & sl);
            o |= (sr | sl);
        }
        sa[lr][wc] = a;
        so[lr][wc] = o;
    }
    __syncthreads();

    // vertical 11-row combine, emit packed edge + target, count edges
    unsigned ecnt = 0u;
    for (int j = tid; j < TR * WPR; j += 256) {
        const int orow = j >> 5, wc = j & 31;
        const int lr = orow + 5;
        unsigned vA = 0xffffffffu, vO = 0u;
        #pragma unroll
        for (int k = -5; k <= 5; k++) {
            vA &= sa[lr + k][wc];
            vO |= so[lr + k][wc];
        }
        const unsigned t = sp[lr][wc];
        const unsigned e = (t & ~vA) | (~t & vO);
        const int gi = (b * IMH + r0 + orow) * WPR + wc;
        g_ebits[gi] = e;
        g_tbits[gi] = t;
        ecnt += __popc(e);
    }

    // reduce edge count
    #pragma unroll
    for (int off = 16; off > 0; off >>= 1)
        ecnt += __shfl_down_sync(0xffffffffu, ecnt, off);
    __shared__ unsigned wsum[8];
    if (lane == 0) wsum[warp] = ecnt;
    __syncthreads();
    if (tid == 0) {
        unsigned s = 0u;
        #pragma unroll
        for (int i = 0; i < 8; i++) s += wsum[i];
        atomicAdd(&g_E, s);
    }
}

// ---------------- kernel 2: fused log-softmax + reductions + finalize -----
__device__ __forceinline__ void proc_px(float x0, float x1, unsigned t, unsigned e,
                                        float& A, float& B) {
    const float m   = fmaxf(x0, x1);
    const float l1p = __logf(1.0f + __expf(-fabsf(x0 - x1)));
    const float lse = m + l1p;
    const float lp0 = x0 - lse;
    const float lp1 = x1 - lse;
    const float lpt = t ? lp1 : lp0;
    A += lpt;
    if (e) B += (lp0 + lp1) - 1.5f * lpt;
}

__device__ __forceinline__ void proc_chunk(const float* __restrict__ s0,
                                           const float* __restrict__ s1,
                                           unsigned p,
                                           float& A0, float& B0,
                                           float& A1, float& B1) {
    const unsigned b   = p >> 20;          // p / HW
    const unsigned pix = p & (HW - 1u);
    const size_t base  = (size_t)b * 2u * HW + pix;

    // streaming (evict-first) loads: keep the 8MB bit arrays L2-resident
    const float4 x0 = __ldcs((const float4*)(s0 + base));
    const float4 y0 = __ldcs((const float4*)(s0 + base + HW));
    const float4 x1 = __ldcs((const float4*)(s1 + base));
    const float4 y1 = __ldcs((const float4*)(s1 + base + HW));

    const unsigned sh = p & 31u;
    const unsigned ew = g_ebits[p >> 5] >> sh;
    const unsigned tw = g_tbits[p >> 5] >> sh;

    proc_px(x0.x, y0.x,  tw       & 1u,  ew       & 1u, A0, B0);
    proc_px(x0.y, y0.y, (tw >> 1) & 1u, (ew >> 1) & 1u, A0, B0);
    proc_px(x0.z, y0.z, (tw >> 2) & 1u, (ew >> 2) & 1u, A0, B0);
    proc_px(x0.w, y0.w, (tw >> 3) & 1u, (ew >> 3) & 1u, A0, B0);

    proc_px(x1.x, y1.x,  tw       & 1u,  ew       & 1u, A1, B1);
    proc_px(x1.y, y1.y, (tw >> 1) & 1u, (ew >> 1) & 1u, A1, B1);
    proc_px(x1.z, y1.z, (tw >> 2) & 1u, (ew >> 2) & 1u, A1, B1);
    proc_px(x1.w, y1.w, (tw >> 3) & 1u, (ew >> 3) & 1u, A1, B1);
}

__global__ __launch_bounds__(256, 6) void main_kernel(const float* __restrict__ s0,
                                                      const float* __restrict__ s1,
                                                      float* __restrict__ out) {
    float A0 = 0.f, B0 = 0.f, A1 = 0.f, B1 = 0.f;
    const unsigned nch    = NPIX / 4u;                 // 4-pixel chunks
    const unsigned stride = MAIN_BLOCKS * 256u;
    unsigned c = blockIdx.x * 256u + threadIdx.x;

    // x2 unrolled grid-stride loop: 8 independent 16B loads in flight
    for (; c + stride < nch; c += 2u * stride) {
        proc_chunk(s0, s1, c * 4u,            A0, B0, A1, B1);
        proc_chunk(s0, s1, (c + stride) * 4u, A0, B0, A1, B1);
    }
    if (c < nch) proc_chunk(s0, s1, c * 4u, A0, B0, A1, B1);

    // block reduction: warp shuffle (float), cross-warp in shared, double atomics
    #pragma unroll
    for (int off = 16; off > 0; off >>= 1) {
        A0 += __shfl_down_sync(0xffffffffu, A0, off);
        B0 += __shfl_down_sync(0xffffffffu, B0, off);
        A1 += __shfl_down_sync(0xffffffffu, A1, off);
        B1 += __shfl_down_sync(0xffffffffu, B1, off);
    }
    __shared__ float red[8][4];
    const int lane = threadIdx.x & 31, warp = threadIdx.x >> 5;
    if (lane == 0) { red[warp][0] = A0; red[warp][1] = B0; red[warp][2] = A1; red[warp][3] = B1; }
    __syncthreads();
    __shared__ bool is_last;
    if (threadIdx.x == 0) {
        double a0 = 0, b0 = 0, a1 = 0, b1 = 0;
        #pragma unroll
        for (int i = 0; i < 8; i++) {
            a0 += (double)red[i][0]; b0 += (double)red[i][1];
            a1 += (double)red[i][2]; b1 += (double)red[i][3];
        }
        atomicAdd(&g_acc[0], a0);
        atomicAdd(&g_acc[1], b0);
        atomicAdd(&g_acc[2], a1);
        atomicAdd(&g_acc[3], b1);
        __threadfence();
        const unsigned t = atomicAdd(&g_ticket, 1u);
        is_last = (t == (unsigned)MAIN_BLOCKS - 1u);
    }
    __syncthreads();

    // last block: finalize scalar and reset accumulators for the next replay
    if (is_last && threadIdx.x == 0) {
        const double N = (double)NPIX;
        double alpha = (double)g_E / N;
        if (alpha > 0.2) alpha = 0.2;
        const double l0 = -(g_acc[0] + alpha * g_acc[1]) / N;
        const double l1 = -(g_acc[2] + alpha * g_acc[3]) / N;
        out[0] = (float)(l0 + 0.5 * l1);
        g_acc[0] = 0.0; g_acc[1] = 0.0; g_acc[2] = 0.0; g_acc[3] = 0.0;
        g_E = 0u;
        __threadfence();
        g_ticket = 0u;
    }
}

// ---------------- launch ---------------------------------------------------
extern "C" void kernel_launch(void* const* d_in, const int* in_sizes, int n_in,
                              void* d_out, int out_size) {
    const float* s0  = (const float*)d_in[0];
    const float* s1  = (const float*)d_in[1];
    const int*   tgt = (const int*)d_in[2];

    edge_kernel<<<dim3(IMH / TR, BATCH), 256>>>(tgt);
    main_kernel<<<MAIN_BLOCKS, 256>>>(s0, s1, (float*)d_out);
}

// round 10
// speedup vs baseline: 1.4920x; 1.4920x over previous
#include <cuda_runtime.h>
#include <cstdint>

#define IMW   1024
#define IMH   1024
#define HW    (1024*1024)
#define BATCH 16
#define NPIX  (16u*1024u*1024u)
#define WPR   32                        // 32-bit words per row (1024/32)
#define TOTAL_WORDS (BATCH * IMH * WPR) // 524288 packed words
#define MAIN_BLOCKS 888                 // 148 SMs * 6 blocks (regs=40), ONE wave

// ---------------- device scratch (static; no allocations) ----------------
// Zero-initialized at module load; main_kernel's last block resets the
// accumulators after each replay, keeping the graph deterministic.
__device__ double        g_acc[4];                 // A0, B0, A1, B1
__device__ unsigned int  g_E;                      // edge pixel count
__device__ unsigned int  g_ticket;                 // last-block ticket
__device__ unsigned int  g_tbits[TOTAL_WORDS];     // packed target     (2 MB)
__device__ unsigned int  g_hand [TOTAL_WORDS];     // horizontal AND-11 (2 MB)
__device__ unsigned int  g_hor  [TOTAL_WORDS];     // horizontal OR-11  (2 MB)
__device__ unsigned int  g_ebits[TOTAL_WORDS];     // packed edge mask  (2 MB)

// ---------------- kernel 1a: pack + horizontal 11-tap AND/OR --------------
// One packed word per thread. Horizontal neighbors are within the same
// 8-row / 256-word block (row edges are image edges -> zero pad), so there
// is NO inter-block halo: the 64MB target is read exactly once.
__global__ __launch_bounds__(256) void edge_h_kernel(const int* __restrict__ target) {
    __shared__ unsigned sp[256];
    const int tid = threadIdx.x;
    const int g   = blockIdx.x * 256 + tid;       // word index in [0, TOTAL_WORDS)
    const int wc  = g & 31;                       // word column within row
    const int row = g >> 5;                       // row in [0, BATCH*IMH)

    // pack 32 pixels: 8 independent int4 streaming loads (128B contiguous)
    unsigned w = 0u;
    const int4* p4 = (const int4*)(target + (size_t)row * IMW + wc * 32);
    #pragma unroll
    for (int k = 0; k < 8; k++) {
        const int4 v = __ldcs(p4 + k);
        w |= (v.x != 0 ? 1u : 0u) << (4 * k);
        w |= (v.y != 0 ? 2u : 0u) << (4 * k);
        w |= (v.z != 0 ? 4u : 0u) << (4 * k);
        w |= (v.w != 0 ? 8u : 0u) << (4 * k);
    }
    sp[tid] = w;
    __syncthreads();

    const unsigned l = (wc > 0)  ? sp[tid - 1] : 0u;   // image-left pad = 0
    const unsigned r = (wc < 31) ? sp[tid + 1] : 0u;   // image-right pad = 0
    unsigned a = w, o = w;
    #pragma unroll
    for (int k = 1; k <= 5; k++) {
        const unsigned sr = __funnelshift_r(w, r, k);  // bit i <- col i+k
        const unsigned sl = __funnelshift_l(l, w, k);  // bit i <- col i-k
        a &= (sr & sl);
        o |= (sr | sl);
    }
    g_tbits[g] = w;
    g_hand[g]  = a;
    g_hor[g]   = o;
}

// ---------------- kernel 1b: vertical 11-row combine + edge count ---------
// One output word per thread; 22 coalesced loads from the 4MB hAND/hOR
// arrays (fully L2-resident -> vertical 11x reuse is L2 traffic, not DRAM).
// edge = (t & ~AND11x11) | (~t & OR11x11); zero-padded rows force AND=0.
__global__ __launch_bounds__(256) void edge_v_kernel() {
    const int tid = threadIdx.x;
    const int g   = blockIdx.x * 256 + tid;
    const int r   = (g >> 5) & (IMH - 1);          // row within image

    unsigned vA = 0xffffffffu, vO = 0u;
    #pragma unroll
    for (int k = -5; k <= 5; k++) {
        const int rr = r + k;
        if (rr >= 0 && rr < IMH) {
            vA &= g_hand[g + k * WPR];
            vO |= g_hor [g + k * WPR];
        } else {
            vA = 0u;                               // zero pad: AND fails
        }
    }
    const unsigned t = g_tbits[g];
    const unsigned e = (t & ~vA) | (~t & vO);
    g_ebits[g] = e;

    // reduce edge count
    unsigned c = __popc(e);
    #pragma unroll
    for (int off = 16; off > 0; off >>= 1)
        c += __shfl_down_sync(0xffffffffu, c, off);
    __shared__ unsigned wsum[8];
    const int lane = tid & 31, warp = tid >> 5;
    if (lane == 0) wsum[warp] = c;
    __syncthreads();
    if (tid == 0) {
        unsigned s = 0u;
        #pragma unroll
        for (int i = 0; i < 8; i++) s += wsum[i];
        atomicAdd(&g_E, s);
    }
}

// ---------------- kernel 2: fused log-softmax + reductions + finalize -----
__device__ __forceinline__ void proc_px(float x0, float x1, unsigned t, unsigned e,
                                        float& A, float& B) {
    const float m   = fmaxf(x0, x1);
    const float l1p = __logf(1.0f + __expf(-fabsf(x0 - x1)));
    const float lse = m + l1p;
    const float lp0 = x0 - lse;
    const float lp1 = x1 - lse;
    const float lpt = t ? lp1 : lp0;
    A += lpt;
    if (e) B += (lp0 + lp1) - 1.5f * lpt;
}

__device__ __forceinline__ void proc_chunk(const float* __restrict__ s0,
                                           const float* __restrict__ s1,
                                           unsigned p,
                                           float& A0, float& B0,
                                           float& A1, float& B1) {
    const unsigned b   = p >> 20;          // p / HW
    const unsigned pix = p & (HW - 1u);
    const size_t base  = (size_t)b * 2u * HW + pix;

    // streaming (evict-first) loads: keep the bit arrays L2-resident
    const float4 x0 = __ldcs((const float4*)(s0 + base));
    const float4 y0 = __ldcs((const float4*)(s0 + base + HW));
    const float4 x1 = __ldcs((const float4*)(s1 + base));
    const float4 y1 = __ldcs((const float4*)(s1 + base + HW));

    const unsigned sh = p & 31u;
    const unsigned ew = g_ebits[p >> 5] >> sh;
    const unsigned tw = g_tbits[p >> 5] >> sh;

    proc_px(x0.x, y0.x,  tw       & 1u,  ew       & 1u, A0, B0);
    proc_px(x0.y, y0.y, (tw >> 1) & 1u, (ew >> 1) & 1u, A0, B0);
    proc_px(x0.z, y0.z, (tw >> 2) & 1u, (ew >> 2) & 1u, A0, B0);
    proc_px(x0.w, y0.w, (tw >> 3) & 1u, (ew >> 3) & 1u, A0, B0);

    proc_px(x1.x, y1.x,  tw       & 1u,  ew       & 1u, A1, B1);
    proc_px(x1.y, y1.y, (tw >> 1) & 1u, (ew >> 1) & 1u, A1, B1);
    proc_px(x1.z, y1.z, (tw >> 2) & 1u, (ew >> 2) & 1u, A1, B1);
    proc_px(x1.w, y1.w, (tw >> 3) & 1u, (ew >> 3) & 1u, A1, B1);
}

__global__ __launch_bounds__(256, 6) void main_kernel(const float* __restrict__ s0,
                                                      const float* __restrict__ s1,
                                                      float* __restrict__ out) {
    float A0 = 0.f, B0 = 0.f, A1 = 0.f, B1 = 0.f;
    const unsigned nch    = NPIX / 4u;                 // 4-pixel chunks
    const unsigned stride = MAIN_BLOCKS * 256u;
    unsigned c = blockIdx.x * 256u + threadIdx.x;

    // x2 unrolled grid-stride loop: 8 independent 16B loads in flight
    for (; c + stride < nch; c += 2u * stride) {
        proc_chunk(s0, s1, c * 4u,            A0, B0, A1, B1);
        proc_chunk(s0, s1, (c + stride) * 4u, A0, B0, A1, B1);
    }
    if (c < nch) proc_chunk(s0, s1, c * 4u, A0, B0, A1, B1);

    // block reduction: warp shuffle (float), cross-warp in shared, double atomics
    #pragma unroll
    for (int off = 16; off > 0; off >>= 1) {
        A0 += __shfl_down_sync(0xffffffffu, A0, off);
        B0 += __shfl_down_sync(0xffffffffu, B0, off);
        A1 += __shfl_down_sync(0xffffffffu, A1, off);
        B1 += __shfl_down_sync(0xffffffffu, B1, off);
    }
    __shared__ float red[8][4];
    const int lane = threadIdx.x & 31, warp = threadIdx.x >> 5;
    if (lane == 0) { red[warp][0] = A0; red[warp][1] = B0; red[warp][2] = A1; red[warp][3] = B1; }
    __syncthreads();
    __shared__ bool is_last;
    if (threadIdx.x == 0) {
        double a0 = 0, b0 = 0, a1 = 0, b1 = 0;
        #pragma unroll
        for (int i = 0; i < 8; i++) {
            a0 += (double)red[i][0]; b0 += (double)red[i][1];
            a1 += (double)red[i][2]; b1 += (double)red[i][3];
        }
        atomicAdd(&g_acc[0], a0);
        atomicAdd(&g_acc[1], b0);
        atomicAdd(&g_acc[2], a1);
        atomicAdd(&g_acc[3], b1);
        __threadfence();
        const unsigned t = atomicAdd(&g_ticket, 1u);
        is_last = (t == (unsigned)MAIN_BLOCKS - 1u);
    }
    __syncthreads();

    // last block: finalize scalar and reset accumulators for the next replay
    if (is_last && threadIdx.x == 0) {
        const double N = (double)NPIX;
        double alpha = (double)g_E / N;
        if (alpha > 0.2) alpha = 0.2;
        const double l0 = -(g_acc[0] + alpha * g_acc[1]) / N;
        const double l1 = -(g_acc[2] + alpha * g_acc[3]) / N;
        out[0] = (float)(l0 + 0.5 * l1);
        g_acc[0] = 0.0; g_acc[1] = 0.0; g_acc[2] = 0.0; g_acc[3] = 0.0;
        g_E = 0u;
        __threadfence();
        g_ticket = 0u;
    }
}

// ---------------- launch ---------------------------------------------------
extern "C" void kernel_launch(void* const* d_in, const int* in_sizes, int n_in,
                              void* d_out, int out_size) {
    const float* s0  = (const float*)d_in[0];
    const float* s1  = (const float*)d_in[1];
    const int*   tgt = (const int*)d_in[2];

    edge_h_kernel<<<TOTAL_WORDS / 256, 256>>>(tgt);
    edge_v_kernel<<<TOTAL_WORDS / 256, 256>>>();
    main_kernel<<<MAIN_BLOCKS, 256>>>(s0, s1, (float*)d_out);
}

// round 11
// speedup vs baseline: 1.5726x; 1.0541x over previous
#include <cuda_runtime.h>
#include <cstdint>

#define IMW   1024
#define IMH   1024
#define HW    (1024*1024)
#define BATCH 16
#define NPIX  (16u*1024u*1024u)
#define WPR   32                        // 32-bit words per row (1024/32)
#define TOTAL_WORDS (BATCH * IMH * WPR) // 524288 packed words
#define MAIN_BLOCKS 888                 // 148 SMs * 6 blocks, ONE wave

// ---------------- device scratch (static; no allocations) ----------------
__device__ double        g_acc[4];                 // A0, B0, A1, B1
__device__ unsigned int  g_E;                      // edge pixel count
__device__ unsigned int  g_ticket;                 // last-block ticket
__device__ unsigned int  g_tbits[TOTAL_WORDS];     // packed target     (2 MB)
__device__ unsigned int  g_hand [TOTAL_WORDS];     // horizontal AND-11 (2 MB)
__device__ unsigned int  g_hor  [TOTAL_WORDS];     // horizontal OR-11  (2 MB)
__device__ unsigned int  g_ebits[TOTAL_WORDS];     // packed edge mask  (2 MB)

// spread 8 bits so bit k lands at bit 4k
__device__ __forceinline__ unsigned spread4(unsigned x) {
    x = (x | (x << 12)) & 0x000F000Fu;
    x = (x | (x << 6))  & 0x03030303u;
    x = (x | (x << 3))  & 0x11111111u;
    return x;
}

// ---------------- kernel 1a: pack + horizontal 11-tap AND/OR --------------
// Coalesced: each warp reads 512 contiguous bytes per iteration (4 L1
// wavefronts per LDG.128 instead of 32), packs via ballot + bit-spread.
__global__ __launch_bounds__(256) void edge_h_kernel(const int* __restrict__ target) {
    __shared__ unsigned sp[256];
    const int tid  = threadIdx.x;
    const int lane = tid & 31;
    const int warp = tid >> 5;
    const int gw0  = blockIdx.x * 256;             // first word of this block
    // warp w owns words [w*32, w*32+32) = pixels [w*1024, (w+1)*1024)
    const size_t pixbase = (size_t)gw0 * 32 + (size_t)warp * 1024;

    #pragma unroll
    for (int i = 0; i < 8; i++) {
        const int4 v = __ldcs((const int4*)(target + pixbase + i * 128) + lane);
        const unsigned b0 = __ballot_sync(0xffffffffu, v.x != 0);
        const unsigned b1 = __ballot_sync(0xffffffffu, v.y != 0);
        const unsigned b2 = __ballot_sync(0xffffffffu, v.z != 0);
        const unsigned b3 = __ballot_sync(0xffffffffu, v.w != 0);
        if (lane < 4) {
            // word j of this 128-pixel chunk: byte j of each ballot,
            // bit k of byte -> pixel 4k+c
            const unsigned w = spread4((b0 >> (8 * lane)) & 0xFFu)
                             | (spread4((b1 >> (8 * lane)) & 0xFFu) << 1)
                             | (spread4((b2 >> (8 * lane)) & 0xFFu) << 2)
                             | (spread4((b3 >> (8 * lane)) & 0xFFu) << 3);
            sp[warp * 32 + i * 4 + lane] = w;
        }
    }
    __syncthreads();

    // horizontal 11-tap AND/OR (neighbors within the row; image edges pad 0)
    const int g  = gw0 + tid;
    const int wc = g & 31;
    const unsigned w = sp[tid];
    const unsigned l = (wc > 0)  ? sp[tid - 1] : 0u;
    const unsigned r = (wc < 31) ? sp[tid + 1] : 0u;
    unsigned a = w, o = w;
    #pragma unroll
    for (int k = 1; k <= 5; k++) {
        const unsigned sr = __funnelshift_r(w, r, k);
        const unsigned sl = __funnelshift_l(l, w, k);
        a &= (sr & sl);
        o |= (sr | sl);
    }
    g_tbits[g] = w;
    g_hand[g]  = a;
    g_hor[g]   = o;
}

// ---------------- kernel 1b: vertical 11-row combine + edge count ---------
__global__ __launch_bounds__(256) void edge_v_kernel() {
    const int tid = threadIdx.x;
    const int g   = blockIdx.x * 256 + tid;
    const int r   = (g >> 5) & (IMH - 1);          // row within image

    unsigned vA = 0xffffffffu, vO = 0u;
    #pragma unroll
    for (int k = -5; k <= 5; k++) {
        const int rr = r + k;
        if (rr >= 0 && rr < IMH) {
            vA &= g_hand[g + k * WPR];
            vO |= g_hor [g + k * WPR];
        } else {
            vA = 0u;                               // zero pad: AND fails
        }
    }
    const unsigned t = g_tbits[g];
    const unsigned e = (t & ~vA) | (~t & vO);
    g_ebits[g] = e;

    unsigned c = __popc(e);
    #pragma unroll
    for (int off = 16; off > 0; off >>= 1)
        c += __shfl_down_sync(0xffffffffu, c, off);
    __shared__ unsigned wsum[8];
    const int lane = tid & 31, warp = tid >> 5;
    if (lane == 0) wsum[warp] = c;
    __syncthreads();
    if (tid == 0) {
        unsigned s = 0u;
        #pragma unroll
        for (int i = 0; i < 8; i++) s += wsum[i];
        atomicAdd(&g_E, s);
    }
}

// ---------------- kernel 2: fused log-softmax + reductions + finalize -----
// With d = x1-x0, sp = softplus(d) = max(d,0)+log1p(exp(-|d|)):
//   lpt             = t*d - sp
//   lp0+lp1-1.5*lpt = d*(1-1.5t) - 0.5*sp
__device__ __forceinline__ void proc_px(float x0, float x1, float tf, float ef,
                                        float& A, float& B) {
    const float d  = x1 - x0;
    const float sp = fmaxf(d, 0.f) + __logf(1.f + __expf(-fabsf(d)));
    A = fmaf(tf, d, A) - sp;
    B = fmaf(ef, fmaf(d, fmaf(-1.5f, tf, 1.f), -0.5f * sp), B);
}

__device__ __forceinline__ void proc_chunk(const float* __restrict__ s0,
                                           const float* __restrict__ s1,
                                           unsigned p,
                                           float& A0, float& B0,
                                           float& A1, float& B1) {
    const unsigned b   = p >> 20;          // p / HW
    const unsigned pix = p & (HW - 1u);
    const size_t base  = (size_t)b * 2u * HW + pix;

    const float4 x0 = __ldcs((const float4*)(s0 + base));
    const float4 y0 = __ldcs((const float4*)(s0 + base + HW));
    const float4 x1 = __ldcs((const float4*)(s1 + base));
    const float4 y1 = __ldcs((const float4*)(s1 + base + HW));

    const unsigned sh = p & 31u;
    const unsigned ew = g_ebits[p >> 5] >> sh;
    const unsigned tw = g_tbits[p >> 5] >> sh;

    const float t0 = (float)( tw       & 1u), e0 = (float)( ew       & 1u);
    const float t1 = (float)((tw >> 1) & 1u), e1 = (float)((ew >> 1) & 1u);
    const float t2 = (float)((tw >> 2) & 1u), e2 = (float)((ew >> 2) & 1u);
    const float t3 = (float)((tw >> 3) & 1u), e3 = (float)((ew >> 3) & 1u);

    proc_px(x0.x, y0.x, t0, e0, A0, B0);
    proc_px(x0.y, y0.y, t1, e1, A0, B0);
    proc_px(x0.z, y0.z, t2, e2, A0, B0);
    proc_px(x0.w, y0.w, t3, e3, A0, B0);

    proc_px(x1.x, y1.x, t0, e0, A1, B1);
    proc_px(x1.y, y1.y, t1, e1, A1, B1);
    proc_px(x1.z, y1.z, t2, e2, A1, B1);
    proc_px(x1.w, y1.w, t3, e3, A1, B1);
}

__global__ __launch_bounds__(256, 6) void main_kernel(const float* __restrict__ s0,
                                                      const float* __restrict__ s1,
                                                      float* __restrict__ out) {
    float A0 = 0.f, B0 = 0.f, A1 = 0.f, B1 = 0.f;
    const unsigned nch    = NPIX / 4u;                 // 4-pixel chunks
    const unsigned stride = MAIN_BLOCKS * 256u;
    unsigned c = blockIdx.x * 256u + threadIdx.x;

    for (; c + stride < nch; c += 2u * stride) {
        proc_chunk(s0, s1, c * 4u,            A0, B0, A1, B1);
        proc_chunk(s0, s1, (c + stride) * 4u, A0, B0, A1, B1);
    }
    if (c < nch) proc_chunk(s0, s1, c * 4u, A0, B0, A1, B1);

    #pragma unroll
    for (int off = 16; off > 0; off >>= 1) {
        A0 += __shfl_down_sync(0xffffffffu, A0, off);
        B0 += __shfl_down_sync(0xffffffffu, B0, off);
        A1 += __shfl_down_sync(0xffffffffu, A1, off);
        B1 += __shfl_down_sync(0xffffffffu, B1, off);
    }
    __shared__ float red[8][4];
    const int lane = threadIdx.x & 31, warp = threadIdx.x >> 5;
    if (lane == 0) { red[warp][0] = A0; red[warp][1] = B0; red[warp][2] = A1; red[warp][3] = B1; }
    __syncthreads();
    __shared__ bool is_last;
    if (threadIdx.x == 0) {
        double a0 = 0, b0 = 0, a1 = 0, b1 = 0;
        #pragma unroll
        for (int i = 0; i < 8; i++) {
            a0 += (double)red[i][0]; b0 += (double)red[i][1];
            a1 += (double)red[i][2]; b1 += (double)red[i][3];
        }
        atomicAdd(&g_acc[0], a0);
        atomicAdd(&g_acc[1], b0);
        atomicAdd(&g_acc[2], a1);
        atomicAdd(&g_acc[3], b1);
        __threadfence();
        const unsigned t = atomicAdd(&g_ticket, 1u);
        is_last = (t == (unsigned)MAIN_BLOCKS - 1u);
    }
    __syncthreads();

    if (is_last && threadIdx.x == 0) {
        const double N = (double)NPIX;
        double alpha = (double)g_E / N;
        if (alpha > 0.2) alpha = 0.2;
        const double l0 = -(g_acc[0] + alpha * g_acc[1]) / N;
        const double l1 = -(g_acc[2] + alpha * g_acc[3]) / N;
        out[0] = (float)(l0 + 0.5 * l1);
        g_acc[0] = 0.0; g_acc[1] = 0.0; g_acc[2] = 0.0; g_acc[3] = 0.0;
        g_E = 0u;
        __threadfence();
        g_ticket = 0u;
    }
}

// ---------------- launch ---------------------------------------------------
extern "C" void kernel_launch(void* const* d_in, const int* in_sizes, int n_in,
                              void* d_out, int out_size) {
    const float* s0  = (const float*)d_in[0];
    const float* s1  = (const float*)d_in[1];
    const int*   tgt = (const int*)d_in[2];

    edge_h_kernel<<<TOTAL_WORDS / 256, 256>>>(tgt);
    edge_v_kernel<<<TOTAL_WORDS / 256, 256>>>();
    main_kernel<<<MAIN_BLOCKS, 256>>>(s0, s1, (float*)d_out);
}